// round 14
// baseline (speedup 1.0000x reference)
#include <cuda_runtime.h>
#include <cuda_fp16.h>
#include <cstdint>

// ---------------------------------------------------------------------------
// Problem constants
// ---------------------------------------------------------------------------
constexpr int Bc = 8, Tc = 12, Nc = 512;
constexpr int BT = Bc * Tc;                 // 96
constexpr int GM = BT * Nc;                 // 49152 rows
constexpr int GN = 512;
constexpr int GK = 512;
constexpr int KH = 8;

// Scratch (allocation-free rule: __device__ globals)
__device__ __half g_x [(size_t)GM * GK];
__device__ __half g_q [(size_t)GM * GK];
__device__ __half g_k [(size_t)GM * GK];
__device__ __half g_v [(size_t)GM * GK];
__device__ __half g_ao[(size_t)GM * GK];
__device__ __half g_h [(size_t)GM * GK];
__device__ __half g_w2[5 * (size_t)GN * GK];   // fp16 weights, [n][k]

__device__ __forceinline__ uint32_t smem_to_u32(const void* p) {
    uint32_t a;
    asm("{ .reg .u64 t; cvta.to.shared.u64 t, %1; cvt.u32.u64 %0, t; }" : "=r"(a) : "l"(p));
    return a;
}

// ---------------------------------------------------------------------------
// Portable tensor-core primitives (sm_80+ ISA)
// ---------------------------------------------------------------------------
__device__ __forceinline__ void ldsm_x4(uint32_t& r0, uint32_t& r1, uint32_t& r2, uint32_t& r3,
                                        uint32_t addr) {
    asm volatile("ldmatrix.sync.aligned.m8n8.x4.shared.b16 {%0,%1,%2,%3}, [%4];"
                 : "=r"(r0), "=r"(r1), "=r"(r2), "=r"(r3) : "r"(addr));
}
__device__ __forceinline__ void ldsm_x4_t(uint32_t& r0, uint32_t& r1, uint32_t& r2, uint32_t& r3,
                                          uint32_t addr) {
    asm volatile("ldmatrix.sync.aligned.m8n8.x4.trans.shared.b16 {%0,%1,%2,%3}, [%4];"
                 : "=r"(r0), "=r"(r1), "=r"(r2), "=r"(r3) : "r"(addr));
}
__device__ __forceinline__ void mma16816(float* d, const uint32_t* a, const uint32_t* b) {
    asm volatile("mma.sync.aligned.m16n8k16.row.col.f32.f16.f16.f32 "
                 "{%0,%1,%2,%3}, {%4,%5,%6,%7}, {%8,%9}, {%0,%1,%2,%3};"
                 : "+f"(d[0]), "+f"(d[1]), "+f"(d[2]), "+f"(d[3])
                 : "r"(a[0]), "r"(a[1]), "r"(a[2]), "r"(a[3]), "r"(b[0]), "r"(b[1]));
}
// fp16-accumulated variant: D/C are 2 x f16x2 regs; D-fragment layout matches
// the A-fragment layout of a following MMA.
__device__ __forceinline__ void mma16816_h(uint32_t* d, const uint32_t* a, const uint32_t* b) {
    asm volatile("mma.sync.aligned.m16n8k16.row.col.f16.f16.f16.f16 "
                 "{%0,%1}, {%2,%3,%4,%5}, {%6,%7}, {%0,%1};"
                 : "+r"(d[0]), "+r"(d[1])
                 : "r"(a[0]), "r"(a[1]), "r"(a[2]), "r"(a[3]), "r"(b[0]), "r"(b[1]));
}
__device__ __forceinline__ void cp_async16(uint32_t smem_addr, const void* gptr) {
    asm volatile("cp.async.cg.shared.global [%0], [%1], 16;" :: "r"(smem_addr), "l"(gptr));
}
#define CP_COMMIT() asm volatile("cp.async.commit_group;" ::: "memory")
#define CP_WAIT(n)  asm volatile("cp.async.wait_group %0;" :: "n"(n) : "memory")

__device__ __forceinline__ uint32_t pack_f16x2(float lo, float hi) {
    uint32_t r;
    asm("cvt.rn.f16x2.f32 %0, %1, %2;" : "=r"(r) : "f"(hi), "f"(lo));
    return r;
}
__device__ __forceinline__ uint32_t ex2_f16x2(uint32_t x) {
    uint32_t r;
    asm("ex2.approx.f16x2 %0, %1;" : "=r"(r) : "r"(x));
    return r;
}

// ---------------------------------------------------------------------------
// Conversion kernels
// ---------------------------------------------------------------------------
__global__ __launch_bounds__(256) void conv_x(const float* __restrict__ A,
                                              __half* __restrict__ Ah) {
    size_t i = (size_t)blockIdx.x * 256 + threadIdx.x;   // over GM*64
    size_t base = i * 8;
    float4 a0 = *(const float4*)(A + base);
    float4 a1 = *(const float4*)(A + base + 4);
    __half h[8];
    h[0] = __float2half_rn(a0.x); h[1] = __float2half_rn(a0.y);
    h[2] = __float2half_rn(a0.z); h[3] = __float2half_rn(a0.w);
    h[4] = __float2half_rn(a1.x); h[5] = __float2half_rn(a1.y);
    h[6] = __float2half_rn(a1.z); h[7] = __float2half_rn(a1.w);
    *(uint4*)(Ah + base) = *(uint4*)h;
}

// 5 weights fused: W[512k][512n] fp32 -> fp16 [n][k]
__global__ __launch_bounds__(256) void conv_w5(const float* __restrict__ W0,
                                               const float* __restrict__ W1,
                                               const float* __restrict__ W2,
                                               const float* __restrict__ W3,
                                               const float* __restrict__ W4,
                                               __half* __restrict__ dst) {
    const int z = blockIdx.y;
    const float* W = (z == 0) ? W0 : (z == 1) ? W1 : (z == 2) ? W2 : (z == 3) ? W3 : W4;
    __half* d = dst + (size_t)z * GN * GK;
    int i = blockIdx.x * 256 + threadIdx.x;   // 512*512
    int k = i >> 9, n = i & 511;
    d[(size_t)n * GK + k] = __float2half_rn(W[i]);
}

// ---------------------------------------------------------------------------
// HMMA GEMM: CTA 256x128, 256 threads (4x2 warps of 64x64), 1 CTA/SM,
// 4-stage cp.async. Bigger M-tile halves L2 traffic per MAC (LTS-cap fix):
// 0.0234 B/MAC -> LTS ceiling ~85% of tensor peak (was 64% at 128x128).
// scale0: extra output scale applied when z == 0 (folds exp constant into q).
// ---------------------------------------------------------------------------
constexpr int BM = 256, BN = 128, BK = 64;
constexpr int KST = 72;                       // padded smem stride (fp16 elems)
constexpr int NIT = GK / BK;                  // 8
constexpr int NSTG = 4;
constexpr int STG_ELEMS = (BM + BN) * KST;    // 27648
constexpr int GEMM_DSMEM = NSTG * STG_ELEMS * 2;  // 221184 B (1 CTA/SM)

template <bool RELU, bool F32OUT, int NZ>
__global__ __launch_bounds__(256)
void gemm_mma(const __half* __restrict__ A,
              const __half* __restrict__ B0, const __half* __restrict__ B1,
              const __half* __restrict__ B2,
              const float* __restrict__ bias0, const float* __restrict__ bias1,
              const float* __restrict__ bias2,
              float* __restrict__ F,
              __half* __restrict__ H0, __half* __restrict__ H1, __half* __restrict__ H2,
              float scale0)
{
    const int z  = (NZ == 1) ? 0 : ((int)blockIdx.x % NZ);
    const int nb = (NZ == 1) ? (int)blockIdx.x : ((int)blockIdx.x / NZ);
    const __half* Bw  = (z == 0) ? B0 : (z == 1) ? B1 : B2;
    const float* bias = (z == 0) ? bias0 : (z == 1) ? bias1 : bias2;
    __half* Ho        = (z == 0) ? H0 : (z == 1) ? H1 : H2;
    const float sc    = (z == 0) ? scale0 : 1.0f;

    extern __shared__ __align__(16) __half dynsm[];
    const uint32_t sbase = smem_to_u32(dynsm);

    const int tid = threadIdx.x;
    const int wid = tid >> 5;
    const int lid = tid & 31;
    const int m0 = (wid >> 1) * 64;       // 4 m-warps
    const int n0 = (wid & 1) * 64;        // 2 n-warps

    const size_t mBase = (size_t)blockIdx.y * BM;
    const size_t nBase = (size_t)nb * BN;
    const __half* Ag = A + mBase * GK;
    const __half* Bg = Bw + nBase * GK;

    auto load_stage = [&](int buf, int it) {
        const int k0 = it * BK;
        const uint32_t aOff = sbase + (uint32_t)(buf * STG_ELEMS) * 2;
        const uint32_t bOff = aOff + (uint32_t)(BM * KST) * 2;
        // A: 256 rows x 8 chunks = 2048; 8 per thread
#pragma unroll
        for (int p = 0; p < 8; p++) {
            int idx = tid + p * 256;
            int r = idx >> 3, u = (idx & 7) * 8;
            cp_async16(aOff + (uint32_t)((r * KST + u) * 2), Ag + (size_t)r * GK + k0 + u);
        }
        // B: 128 rows x 8 chunks = 1024; 4 per thread
#pragma unroll
        for (int p = 0; p < 4; p++) {
            int idx = tid + p * 256;
            int r = idx >> 3, u = (idx & 7) * 8;
            cp_async16(bOff + (uint32_t)((r * KST + u) * 2), Bg + (size_t)r * GK + k0 + u);
        }
        CP_COMMIT();
    };

    float acc[4][8][4];
#pragma unroll
    for (int i = 0; i < 4; i++)
#pragma unroll
        for (int j = 0; j < 8; j++)
#pragma unroll
            for (int c = 0; c < 4; c++) acc[i][j][c] = 0.0f;

    const int seg = lid >> 3, lrow = lid & 7;
    const int a_roff = lrow + ((seg & 1) << 3);
    const int a_coff = (seg >> 1) << 3;
    const int b_roff = lrow + ((seg >> 1) << 3);
    const int b_coff = (seg & 1) << 3;

    load_stage(0, 0);
    load_stage(1, 1);
    load_stage(2, 2);

#pragma unroll
    for (int it = 0; it < NIT; ++it) {
        CP_WAIT(2);
        __syncthreads();
        if (it + 3 < NIT) load_stage((it + 3) % NSTG, it + 3);

        const uint32_t aB = sbase + (uint32_t)((it % NSTG) * STG_ELEMS) * 2;
        const uint32_t bB = aB + (uint32_t)(BM * KST) * 2;

#pragma unroll
        for (int kk = 0; kk < 4; kk++) {
            uint32_t ra[4][4], rb[4][4];
#pragma unroll
            for (int mi = 0; mi < 4; mi++) {
                uint32_t addr = aB + (uint32_t)(((m0 + mi * 16 + a_roff) * KST + kk * 16 + a_coff) * 2);
                ldsm_x4(ra[mi][0], ra[mi][1], ra[mi][2], ra[mi][3], addr);
            }
#pragma unroll
            for (int g = 0; g < 4; g++) {
                uint32_t addr = bB + (uint32_t)(((n0 + g * 16 + b_roff) * KST + kk * 16 + b_coff) * 2);
                ldsm_x4(rb[g][0], rb[g][1], rb[g][2], rb[g][3], addr);
            }
#pragma unroll
            for (int mi = 0; mi < 4; mi++)
#pragma unroll
                for (int g = 0; g < 4; g++) {
                    mma16816(acc[mi][2 * g],     ra[mi], &rb[g][0]);
                    mma16816(acc[mi][2 * g + 1], ra[mi], &rb[g][2]);
                }
        }
    }

    // epilogue
    const int gr = lid >> 2;
    const int gc = (lid & 3) * 2;
#pragma unroll
    for (int mi = 0; mi < 4; mi++) {
        const size_t row0 = mBase + m0 + mi * 16 + gr;
#pragma unroll
        for (int nj = 0; nj < 8; nj++) {
            const int col = (int)nBase + n0 + nj * 8 + gc;
            const float bx = __ldg(&bias[col]);
            const float by = __ldg(&bias[col + 1]);
            float v0 = acc[mi][nj][0] + bx;
            float v1 = acc[mi][nj][1] + by;
            float v2 = acc[mi][nj][2] + bx;
            float v3 = acc[mi][nj][3] + by;
            if (RELU) {
                v0 = fmaxf(v0, 0.f); v1 = fmaxf(v1, 0.f);
                v2 = fmaxf(v2, 0.f); v3 = fmaxf(v3, 0.f);
            }
            v0 *= sc; v1 *= sc; v2 *= sc; v3 *= sc;
            if (F32OUT) {
                *(float2*)(F + row0 * GN + col)       = make_float2(v0, v1);
                *(float2*)(F + (row0 + 8) * GN + col) = make_float2(v2, v3);
            } else {
                *(uint32_t*)(Ho + row0 * GN + col)       = pack_f16x2(v0, v1);
                *(uint32_t*)(Ho + (row0 + 8) * GN + col) = pack_f16x2(v2, v3);
            }
        }
    }
}

// ---------------------------------------------------------------------------
// HMMA flash attention (R13 winner, frozen): CTA = 128 queries of one head,
// 256 threads, 8 warps of 16x64, 2 CTA/SM, 4-stage KV pipeline.
// fp16-accumulated S (D-fragment == PV A-fragment), packed ex2 softmax,
// rowsum via constant ones-fragment, q pre-scaled by 0.125*log2(e).
// Grid: x = q-block (4, fast -> KV L2 reuse), y = head (768).
// ---------------------------------------------------------------------------
constexpr int AST = 72;                       // smem row stride (fp16)
constexpr int SQ = 0;
constexpr int SKV0 = 128 * AST;
constexpr int ASTG = 2 * 64 * AST;            // per-stage elems (k, v)
constexpr int ANSTG = 4;
constexpr int ATT_DSMEM = (SKV0 + ANSTG * ASTG) * 2;  // 92160 B (2 CTA = 180 KB)

__global__ __launch_bounds__(256, 2)
void attn_mma(const __half* __restrict__ qg, const __half* __restrict__ kg,
              const __half* __restrict__ vg, __half* __restrict__ og)
{
    extern __shared__ __align__(16) __half smb[];
    const uint32_t sb = smem_to_u32(smb);

    const int tid = threadIdx.x;
    const int wid = tid >> 5;
    const int lid = tid & 31;
    const int m0 = wid * 16;

    const int head = blockIdx.y;
    const int bt = head >> 3;
    const int hk = head & 7;
    const size_t qrow0 = (size_t)bt * 512 + blockIdx.x * 128;
    const size_t krow0 = (size_t)bt * 512;
    const int colb = hk * 64;

    const int seg = lid >> 3, lrow = lid & 7;
    const int a_roff = lrow + ((seg & 1) << 3);
    const int a_coff = (seg >> 1) << 3;
    const int b_roff = lrow + ((seg >> 1) << 3);
    const int b_coff = (seg & 1) << 3;
    const int v_roff = lrow + ((seg & 1) << 3);
    const int v_coff = (seg >> 1) << 3;

    // ---- stage Q (own commit group) ----
    {
#pragma unroll
        for (int t = 0; t < 4; t++) {
            int c = tid + t * 256;              // 1024 chunks
            int r = c >> 3, u = (c & 7) * 8;
            cp_async16(sb + (uint32_t)((SQ + r * AST + u) * 2),
                       qg + (qrow0 + r) * 512 + colb + u);
        }
        CP_COMMIT();
    }
    auto stage_kv = [&](int kt) {
        const size_t kr = krow0 + kt * 64;
        const uint32_t b = SKV0 + (kt % ANSTG) * ASTG;
#pragma unroll
        for (int t = 0; t < 2; t++) {
            int c = tid + t * 256;              // 512 chunks per array
            int r = c >> 3, u = (c & 7) * 8;
            cp_async16(sb + (uint32_t)((b + r * AST + u) * 2),
                       kg + (kr + r) * 512 + colb + u);
            cp_async16(sb + (uint32_t)((b + 64 * AST + r * AST + u) * 2),
                       vg + (kr + r) * 512 + colb + u);
        }
        CP_COMMIT();
    };

    stage_kv(0);
    stage_kv(1);
    stage_kv(2);
    CP_WAIT(3);          // Q complete (oldest of 4 groups)
    __syncthreads();

    // ---- Q fragments ----
    uint32_t qf[4][4];
#pragma unroll
    for (int ks = 0; ks < 4; ks++)
        ldsm_x4(qf[ks][0], qf[ks][1], qf[ks][2], qf[ks][3],
                sb + (uint32_t)(((SQ + (m0 + a_roff) * AST) + ks * 16 + a_coff) * 2));

    float oacc[8][4];
#pragma unroll
    for (int j = 0; j < 8; j++)
#pragma unroll
        for (int c = 0; c < 4; c++) oacc[j][c] = 0.0f;
    float oex[4] = {0.f, 0.f, 0.f, 0.f};       // rowsum via ones-fragment

    // ones B-fragment: local col 0 = 1.0 for all k -> lanes 0-3 hold 1.0h pairs
    const uint32_t vxc = (lid < 4) ? 0x3C003C00u : 0u;
    uint32_t vxa[2] = {vxc, vxc};

#pragma unroll
    for (int kt = 0; kt < 8; kt++) {
        CP_WAIT(2);                 // stage kt ready
        __syncthreads();
        if (kt + 3 < 8) stage_kv(kt + 3);

        const uint32_t base = SKV0 + (kt % ANSTG) * ASTG;

        // --- S = Q K^T in fp16 accumulation (q carries 0.125*log2e) ---
        uint32_t sacc[8][2];
#pragma unroll
        for (int j = 0; j < 8; j++) { sacc[j][0] = 0u; sacc[j][1] = 0u; }

#pragma unroll
        for (int ks = 0; ks < 4; ks++) {
            uint32_t kb[4][4];
#pragma unroll
            for (int j = 0; j < 4; j++)
                ldsm_x4(kb[j][0], kb[j][1], kb[j][2], kb[j][3],
                        sb + (uint32_t)(((base + (j * 16 + b_roff) * AST) + ks * 16 + b_coff) * 2));
#pragma unroll
            for (int j = 0; j < 4; j++) {
                mma16816_h(sacc[2 * j],     qf[ks], &kb[j][0]);
                mma16816_h(sacc[2 * j + 1], qf[ks], &kb[j][2]);
            }
        }

        // --- O += P V, rowsum += P ; P = 2^S via packed ex2 on fragments ---
#pragma unroll
        for (int pk = 0; pk < 4; pk++) {
            uint32_t pa[4];
            pa[0] = ex2_f16x2(sacc[2 * pk][0]);
            pa[1] = ex2_f16x2(sacc[2 * pk][1]);
            pa[2] = ex2_f16x2(sacc[2 * pk + 1][0]);
            pa[3] = ex2_f16x2(sacc[2 * pk + 1][1]);
            uint32_t vb[4][4];
#pragma unroll
            for (int dj = 0; dj < 4; dj++)
                ldsm_x4_t(vb[dj][0], vb[dj][1], vb[dj][2], vb[dj][3],
                          sb + (uint32_t)(((base + 64 * AST + (pk * 16 + v_roff) * AST) + dj * 16 + v_coff) * 2));
#pragma unroll
            for (int dj = 0; dj < 4; dj++) {
                mma16816(oacc[2 * dj],     pa, &vb[dj][0]);
                mma16816(oacc[2 * dj + 1], pa, &vb[dj][2]);
            }
            mma16816(oex, pa, vxa);
        }
    }

    // --- rowsum broadcast from quad lane 0 ---
    const float rsum0 = __shfl_sync(0xFFFFFFFFu, oex[0], lid & ~3);
    const float rsum1 = __shfl_sync(0xFFFFFFFFu, oex[2], lid & ~3);
    const float rinv0 = 1.0f / rsum0;
    const float rinv1 = 1.0f / rsum1;

    // --- normalize + write fp16 ---
    const int gr = lid >> 2;
    const int gc = (lid & 3) * 2;
    const size_t row0 = qrow0 + m0 + gr;
#pragma unroll
    for (int nj = 0; nj < 8; nj++) {
        const int col = colb + nj * 8 + gc;
        *(uint32_t*)(og + row0 * 512 + col) =
            pack_f16x2(oacc[nj][0] * rinv0, oacc[nj][1] * rinv0);
        *(uint32_t*)(og + (row0 + 8) * 512 + col) =
            pack_f16x2(oacc[nj][2] * rinv1, oacc[nj][3] * rinv1);
    }
}

// ---------------------------------------------------------------------------
// Launch
// ---------------------------------------------------------------------------
extern "C" void kernel_launch(void* const* d_in, const int* in_sizes, int n_in,
                              void* d_out, int out_size)
{
    (void)in_sizes; (void)n_in; (void)out_size;
    const float* X  = (const float*)d_in[0];
    const float* Wq = (const float*)d_in[2];
    const float* bq = (const float*)d_in[3];
    const float* Wk = (const float*)d_in[4];
    const float* bk = (const float*)d_in[5];
    const float* Wv = (const float*)d_in[6];
    const float* bv = (const float*)d_in[7];
    const float* W1 = (const float*)d_in[8];
    const float* b1 = (const float*)d_in[9];
    const float* W2 = (const float*)d_in[10];
    const float* b2 = (const float*)d_in[11];
    float* out = (float*)d_out;

    __half *x, *q, *k, *v, *ao, *h, *w2;
    cudaGetSymbolAddress((void**)&x,  g_x);
    cudaGetSymbolAddress((void**)&q,  g_q);
    cudaGetSymbolAddress((void**)&k,  g_k);
    cudaGetSymbolAddress((void**)&v,  g_v);
    cudaGetSymbolAddress((void**)&ao, g_ao);
    cudaGetSymbolAddress((void**)&h,  g_h);
    cudaGetSymbolAddress((void**)&w2, g_w2);
    const size_t WSZ = (size_t)GN * GK;

    cudaFuncSetAttribute((const void*)gemm_mma<true, false, 3>,
                         cudaFuncAttributeMaxDynamicSharedMemorySize, GEMM_DSMEM);
    cudaFuncSetAttribute((const void*)gemm_mma<true, false, 1>,
                         cudaFuncAttributeMaxDynamicSharedMemorySize, GEMM_DSMEM);
    cudaFuncSetAttribute((const void*)gemm_mma<false, true, 1>,
                         cudaFuncAttributeMaxDynamicSharedMemorySize, GEMM_DSMEM);
    cudaFuncSetAttribute((const void*)attn_mma,
                         cudaFuncAttributeMaxDynamicSharedMemorySize, ATT_DSMEM);

    const float CEXP = 0.18033688011112042f;   // 0.125 * log2(e)

    dim3 blk256(256);
    dim3 gX((unsigned)((size_t)GM * 64 / 256));
    dim3 gW(512 * 512 / 256, 5);
    dim3 gQKV(3 * GN / BN, GM / BM);    // (12, 192): z fastest for L2 A-reuse
    dim3 gFC(GN / BN, GM / BM);         // (4, 192)
    dim3 gAtt(4, BT * KH);              // (qblock, head): sharers adjacent

    conv_x<<<gX, blk256>>>(X, x);
    conv_w5<<<gW, blk256>>>(Wq, Wk, Wv, W1, W2, w2);

    // 1) QKV (fp16 out; q scaled by CEXP)
    gemm_mma<true, false, 3><<<gQKV, blk256, GEMM_DSMEM>>>(x, w2, w2 + WSZ, w2 + 2 * WSZ,
                                                           bq, bk, bv, nullptr, q, k, v, CEXP);
    // 2) attention -> ao (fp16)
    attn_mma<<<gAtt, blk256, ATT_DSMEM>>>(q, k, v, ao);
    // 3) FC1 -> h (fp16, ReLU)
    gemm_mma<true, false, 1><<<gFC, blk256, GEMM_DSMEM>>>(ao, w2 + 3 * WSZ, w2 + 3 * WSZ, w2 + 3 * WSZ,
                                                          b1, b1, b1, nullptr, h, h, h, 1.0f);
    // 4) FC2 -> out (fp32)
    gemm_mma<false, true, 1><<<gFC, blk256, GEMM_DSMEM>>>(h, w2 + 4 * WSZ, w2 + 4 * WSZ, w2 + 4 * WSZ,
                                                          b2, b2, b2, out,
                                                          nullptr, nullptr, nullptr, 1.0f);
}

// round 15
// speedup vs baseline: 1.1101x; 1.1101x over previous
#include <cuda_runtime.h>
#include <cuda_fp16.h>
#include <cstdint>

// ---------------------------------------------------------------------------
// Problem constants
// ---------------------------------------------------------------------------
constexpr int Bc = 8, Tc = 12, Nc = 512;
constexpr int BT = Bc * Tc;                 // 96
constexpr int GM = BT * Nc;                 // 49152 rows
constexpr int GN = 512;
constexpr int GK = 512;
constexpr int KH = 8;

// Scratch (allocation-free rule: __device__ globals)
__device__ __half g_x [(size_t)GM * GK];
__device__ __half g_q [(size_t)GM * GK];
__device__ __half g_k [(size_t)GM * GK];
__device__ __half g_v [(size_t)GM * GK];
__device__ __half g_ao[(size_t)GM * GK];
__device__ __half g_h [(size_t)GM * GK];
__device__ __half g_w2[5 * (size_t)GN * GK];   // fp16 weights, [n][k]

__device__ __forceinline__ uint32_t smem_to_u32(const void* p) {
    uint32_t a;
    asm("{ .reg .u64 t; cvta.to.shared.u64 t, %1; cvt.u32.u64 %0, t; }" : "=r"(a) : "l"(p));
    return a;
}

// ---------------------------------------------------------------------------
// Portable tensor-core primitives (sm_80+ ISA)
// ---------------------------------------------------------------------------
__device__ __forceinline__ void ldsm_x4(uint32_t& r0, uint32_t& r1, uint32_t& r2, uint32_t& r3,
                                        uint32_t addr) {
    asm volatile("ldmatrix.sync.aligned.m8n8.x4.shared.b16 {%0,%1,%2,%3}, [%4];"
                 : "=r"(r0), "=r"(r1), "=r"(r2), "=r"(r3) : "r"(addr));
}
__device__ __forceinline__ void ldsm_x4_t(uint32_t& r0, uint32_t& r1, uint32_t& r2, uint32_t& r3,
                                          uint32_t addr) {
    asm volatile("ldmatrix.sync.aligned.m8n8.x4.trans.shared.b16 {%0,%1,%2,%3}, [%4];"
                 : "=r"(r0), "=r"(r1), "=r"(r2), "=r"(r3) : "r"(addr));
}
__device__ __forceinline__ void mma16816(float* d, const uint32_t* a, const uint32_t* b) {
    asm volatile("mma.sync.aligned.m16n8k16.row.col.f32.f16.f16.f32 "
                 "{%0,%1,%2,%3}, {%4,%5,%6,%7}, {%8,%9}, {%0,%1,%2,%3};"
                 : "+f"(d[0]), "+f"(d[1]), "+f"(d[2]), "+f"(d[3])
                 : "r"(a[0]), "r"(a[1]), "r"(a[2]), "r"(a[3]), "r"(b[0]), "r"(b[1]));
}
// fp16-accumulated variant: D/C are 2 x f16x2 regs; D-fragment layout matches
// the A-fragment layout of a following MMA.
__device__ __forceinline__ void mma16816_h(uint32_t* d, const uint32_t* a, const uint32_t* b) {
    asm volatile("mma.sync.aligned.m16n8k16.row.col.f16.f16.f16.f16 "
                 "{%0,%1}, {%2,%3,%4,%5}, {%6,%7}, {%0,%1};"
                 : "+r"(d[0]), "+r"(d[1])
                 : "r"(a[0]), "r"(a[1]), "r"(a[2]), "r"(a[3]), "r"(b[0]), "r"(b[1]));
}
__device__ __forceinline__ void cp_async16(uint32_t smem_addr, const void* gptr) {
    asm volatile("cp.async.cg.shared.global [%0], [%1], 16;" :: "r"(smem_addr), "l"(gptr));
}
#define CP_COMMIT() asm volatile("cp.async.commit_group;" ::: "memory")
#define CP_WAIT(n)  asm volatile("cp.async.wait_group %0;" :: "n"(n) : "memory")

__device__ __forceinline__ uint32_t pack_f16x2(float lo, float hi) {
    uint32_t r;
    asm("cvt.rn.f16x2.f32 %0, %1, %2;" : "=r"(r) : "f"(hi), "f"(lo));
    return r;
}
__device__ __forceinline__ uint32_t ex2_f16x2(uint32_t x) {
    uint32_t r;
    asm("ex2.approx.f16x2 %0, %1;" : "=r"(r) : "r"(x));
    return r;
}

// ---------------------------------------------------------------------------
// Fused conversion kernel: one launch covers X (fp32->fp16) and all 5 weights
// (fp32 [k][n] -> fp16 [n][k]). Block-range switch.
// ---------------------------------------------------------------------------
constexpr unsigned NXBLK = (unsigned)((size_t)GM * 64 / 256);   // 12288
constexpr unsigned NWBLK = 5 * (512 * 512 / 256);               // 5120

__global__ __launch_bounds__(256)
void conv_all(const float* __restrict__ X, __half* __restrict__ Xh,
              const float* __restrict__ W0, const float* __restrict__ W1,
              const float* __restrict__ W2, const float* __restrict__ W3,
              const float* __restrict__ W4, __half* __restrict__ Wdst)
{
    const unsigned b = blockIdx.x;
    if (b < NXBLK) {
        size_t i = (size_t)b * 256 + threadIdx.x;
        size_t base = i * 8;
        float4 a0 = *(const float4*)(X + base);
        float4 a1 = *(const float4*)(X + base + 4);
        __half h[8];
        h[0] = __float2half_rn(a0.x); h[1] = __float2half_rn(a0.y);
        h[2] = __float2half_rn(a0.z); h[3] = __float2half_rn(a0.w);
        h[4] = __float2half_rn(a1.x); h[5] = __float2half_rn(a1.y);
        h[6] = __float2half_rn(a1.z); h[7] = __float2half_rn(a1.w);
        *(uint4*)(Xh + base) = *(uint4*)h;
    } else {
        const unsigned wb = b - NXBLK;           // 0..5119
        const int z = (int)(wb / 1024);          // weight index
        const float* W = (z == 0) ? W0 : (z == 1) ? W1 : (z == 2) ? W2 : (z == 3) ? W3 : W4;
        __half* d = Wdst + (size_t)z * GN * GK;
        int i = (int)(wb % 1024) * 256 + threadIdx.x;   // 512*512
        int k = i >> 9, n = i & 511;
        d[(size_t)n * GK + k] = __float2half_rn(W[i]);
    }
}

// ---------------------------------------------------------------------------
// HMMA GEMM (R13/R9 winner): CTA 128x128, 128 threads (2x2 warps of 64x64),
// 2 CTAs/SM, 3-stage cp.async, fully-unrolled main loop.
// scale0: extra output scale applied when z == 0 (folds exp constant into q).
// ---------------------------------------------------------------------------
constexpr int BM = 128, BN = 128, BK = 64;
constexpr int KST = 72;                       // padded smem stride (fp16 elems)
constexpr int NIT = GK / BK;                  // 8
constexpr int NSTG = 3;
constexpr int STG_ELEMS = (BM + BN) * KST;    // 18432
constexpr int GEMM_DSMEM = NSTG * STG_ELEMS * 2;  // 110592 B (2 CTA = 221 KB)

template <bool RELU, bool F32OUT, int NZ>
__global__ __launch_bounds__(128)
void gemm_mma(const __half* __restrict__ A,
              const __half* __restrict__ B0, const __half* __restrict__ B1,
              const __half* __restrict__ B2,
              const float* __restrict__ bias0, const float* __restrict__ bias1,
              const float* __restrict__ bias2,
              float* __restrict__ F,
              __half* __restrict__ H0, __half* __restrict__ H1, __half* __restrict__ H2,
              float scale0)
{
    const int z  = (NZ == 1) ? 0 : ((int)blockIdx.x % NZ);
    const int nb = (NZ == 1) ? (int)blockIdx.x : ((int)blockIdx.x / NZ);
    const __half* Bw  = (z == 0) ? B0 : (z == 1) ? B1 : B2;
    const float* bias = (z == 0) ? bias0 : (z == 1) ? bias1 : bias2;
    __half* Ho        = (z == 0) ? H0 : (z == 1) ? H1 : H2;
    const float sc    = (z == 0) ? scale0 : 1.0f;

    extern __shared__ __align__(16) __half dynsm[];
    const uint32_t sbase = smem_to_u32(dynsm);

    const int tid = threadIdx.x;
    const int wid = tid >> 5;
    const int lid = tid & 31;
    const int m0 = (wid >> 1) * 64;       // 2 m-warps
    const int n0 = (wid & 1) * 64;        // 2 n-warps

    const size_t mBase = (size_t)blockIdx.y * BM;
    const size_t nBase = (size_t)nb * BN;
    const __half* Ag = A + mBase * GK;
    const __half* Bg = Bw + nBase * GK;

    auto load_stage = [&](int buf, int it) {
        const int k0 = it * BK;
        const uint32_t aOff = sbase + (uint32_t)(buf * STG_ELEMS) * 2;
        const uint32_t bOff = aOff + (uint32_t)(BM * KST) * 2;
#pragma unroll
        for (int p = 0; p < 8; p++) {
            int idx = tid + p * 128;
            int r = idx >> 3, u = (idx & 7) * 8;
            cp_async16(aOff + (uint32_t)((r * KST + u) * 2), Ag + (size_t)r * GK + k0 + u);
        }
#pragma unroll
        for (int p = 0; p < 8; p++) {
            int idx = tid + p * 128;
            int r = idx >> 3, u = (idx & 7) * 8;
            cp_async16(bOff + (uint32_t)((r * KST + u) * 2), Bg + (size_t)r * GK + k0 + u);
        }
        CP_COMMIT();
    };

    float acc[4][8][4];
#pragma unroll
    for (int i = 0; i < 4; i++)
#pragma unroll
        for (int j = 0; j < 8; j++)
#pragma unroll
            for (int c = 0; c < 4; c++) acc[i][j][c] = 0.0f;

    const int seg = lid >> 3, lrow = lid & 7;
    const int a_roff = lrow + ((seg & 1) << 3);
    const int a_coff = (seg >> 1) << 3;
    const int b_roff = lrow + ((seg >> 1) << 3);
    const int b_coff = (seg & 1) << 3;

    load_stage(0, 0);
    load_stage(1, 1);

#pragma unroll
    for (int it = 0; it < NIT; ++it) {
        CP_WAIT(1);
        __syncthreads();
        if (it + 2 < NIT) load_stage((it + 2) % NSTG, it + 2);

        const uint32_t aB = sbase + (uint32_t)((it % NSTG) * STG_ELEMS) * 2;
        const uint32_t bB = aB + (uint32_t)(BM * KST) * 2;

#pragma unroll
        for (int kk = 0; kk < 4; kk++) {
            uint32_t ra[4][4], rb[4][4];
#pragma unroll
            for (int mi = 0; mi < 4; mi++) {
                uint32_t addr = aB + (uint32_t)(((m0 + mi * 16 + a_roff) * KST + kk * 16 + a_coff) * 2);
                ldsm_x4(ra[mi][0], ra[mi][1], ra[mi][2], ra[mi][3], addr);
            }
#pragma unroll
            for (int g = 0; g < 4; g++) {
                uint32_t addr = bB + (uint32_t)(((n0 + g * 16 + b_roff) * KST + kk * 16 + b_coff) * 2);
                ldsm_x4(rb[g][0], rb[g][1], rb[g][2], rb[g][3], addr);
            }
#pragma unroll
            for (int mi = 0; mi < 4; mi++)
#pragma unroll
                for (int g = 0; g < 4; g++) {
                    mma16816(acc[mi][2 * g],     ra[mi], &rb[g][0]);
                    mma16816(acc[mi][2 * g + 1], ra[mi], &rb[g][2]);
                }
        }
    }

    // epilogue (bias hoisted: columns depend only on nj, not mi)
    const int gr = lid >> 2;
    const int gc = (lid & 3) * 2;
    float bx[8], by[8];
#pragma unroll
    for (int nj = 0; nj < 8; nj++) {
        const int col = (int)nBase + n0 + nj * 8 + gc;
        bx[nj] = __ldg(&bias[col]);
        by[nj] = __ldg(&bias[col + 1]);
    }
#pragma unroll
    for (int mi = 0; mi < 4; mi++) {
        const size_t row0 = mBase + m0 + mi * 16 + gr;
#pragma unroll
        for (int nj = 0; nj < 8; nj++) {
            const int col = (int)nBase + n0 + nj * 8 + gc;
            float v0 = acc[mi][nj][0] + bx[nj];
            float v1 = acc[mi][nj][1] + by[nj];
            float v2 = acc[mi][nj][2] + bx[nj];
            float v3 = acc[mi][nj][3] + by[nj];
            if (RELU) {
                v0 = fmaxf(v0, 0.f); v1 = fmaxf(v1, 0.f);
                v2 = fmaxf(v2, 0.f); v3 = fmaxf(v3, 0.f);
            }
            v0 *= sc; v1 *= sc; v2 *= sc; v3 *= sc;
            if (F32OUT) {
                *(float2*)(F + row0 * GN + col)       = make_float2(v0, v1);
                *(float2*)(F + (row0 + 8) * GN + col) = make_float2(v2, v3);
            } else {
                *(uint32_t*)(Ho + row0 * GN + col)       = pack_f16x2(v0, v1);
                *(uint32_t*)(Ho + (row0 + 8) * GN + col) = pack_f16x2(v2, v3);
            }
        }
    }
}

// ---------------------------------------------------------------------------
// HMMA flash attention (R13 winner, frozen): CTA = 128 queries of one head,
// 256 threads, 8 warps of 16x64, 2 CTA/SM, 4-stage KV pipeline.
// fp16-accumulated S (D-fragment == PV A-fragment), packed ex2 softmax,
// rowsum via constant ones-fragment, q pre-scaled by 0.125*log2(e).
// Grid: x = q-block (4, fast -> KV L2 reuse), y = head (768).
// ---------------------------------------------------------------------------
constexpr int AST = 72;                       // smem row stride (fp16)
constexpr int SQ = 0;
constexpr int SKV0 = 128 * AST;
constexpr int ASTG = 2 * 64 * AST;            // per-stage elems (k, v)
constexpr int ANSTG = 4;
constexpr int ATT_DSMEM = (SKV0 + ANSTG * ASTG) * 2;  // 92160 B (2 CTA = 180 KB)

__global__ __launch_bounds__(256, 2)
void attn_mma(const __half* __restrict__ qg, const __half* __restrict__ kg,
              const __half* __restrict__ vg, __half* __restrict__ og)
{
    extern __shared__ __align__(16) __half smb[];
    const uint32_t sb = smem_to_u32(smb);

    const int tid = threadIdx.x;
    const int wid = tid >> 5;
    const int lid = tid & 31;
    const int m0 = wid * 16;

    const int head = blockIdx.y;
    const int bt = head >> 3;
    const int hk = head & 7;
    const size_t qrow0 = (size_t)bt * 512 + blockIdx.x * 128;
    const size_t krow0 = (size_t)bt * 512;
    const int colb = hk * 64;

    const int seg = lid >> 3, lrow = lid & 7;
    const int a_roff = lrow + ((seg & 1) << 3);
    const int a_coff = (seg >> 1) << 3;
    const int b_roff = lrow + ((seg >> 1) << 3);
    const int b_coff = (seg & 1) << 3;
    const int v_roff = lrow + ((seg & 1) << 3);
    const int v_coff = (seg >> 1) << 3;

    // ---- stage Q (own commit group) ----
    {
#pragma unroll
        for (int t = 0; t < 4; t++) {
            int c = tid + t * 256;              // 1024 chunks
            int r = c >> 3, u = (c & 7) * 8;
            cp_async16(sb + (uint32_t)((SQ + r * AST + u) * 2),
                       qg + (qrow0 + r) * 512 + colb + u);
        }
        CP_COMMIT();
    }
    auto stage_kv = [&](int kt) {
        const size_t kr = krow0 + kt * 64;
        const uint32_t b = SKV0 + (kt % ANSTG) * ASTG;
#pragma unroll
        for (int t = 0; t < 2; t++) {
            int c = tid + t * 256;              // 512 chunks per array
            int r = c >> 3, u = (c & 7) * 8;
            cp_async16(sb + (uint32_t)((b + r * AST + u) * 2),
                       kg + (kr + r) * 512 + colb + u);
            cp_async16(sb + (uint32_t)((b + 64 * AST + r * AST + u) * 2),
                       vg + (kr + r) * 512 + colb + u);
        }
        CP_COMMIT();
    };

    stage_kv(0);
    stage_kv(1);
    stage_kv(2);
    CP_WAIT(3);          // Q complete (oldest of 4 groups)
    __syncthreads();

    // ---- Q fragments ----
    uint32_t qf[4][4];
#pragma unroll
    for (int ks = 0; ks < 4; ks++)
        ldsm_x4(qf[ks][0], qf[ks][1], qf[ks][2], qf[ks][3],
                sb + (uint32_t)(((SQ + (m0 + a_roff) * AST) + ks * 16 + a_coff) * 2));

    float oacc[8][4];
#pragma unroll
    for (int j = 0; j < 8; j++)
#pragma unroll
        for (int c = 0; c < 4; c++) oacc[j][c] = 0.0f;
    float oex[4] = {0.f, 0.f, 0.f, 0.f};       // rowsum via ones-fragment

    // ones B-fragment: local col 0 = 1.0 for all k -> lanes 0-3 hold 1.0h pairs
    const uint32_t vxc = (lid < 4) ? 0x3C003C00u : 0u;
    uint32_t vxa[2] = {vxc, vxc};

#pragma unroll
    for (int kt = 0; kt < 8; kt++) {
        CP_WAIT(2);                 // stage kt ready
        __syncthreads();
        if (kt + 3 < 8) stage_kv(kt + 3);

        const uint32_t base = SKV0 + (kt % ANSTG) * ASTG;

        // --- S = Q K^T in fp16 accumulation (q carries 0.125*log2e) ---
        uint32_t sacc[8][2];
#pragma unroll
        for (int j = 0; j < 8; j++) { sacc[j][0] = 0u; sacc[j][1] = 0u; }

#pragma unroll
        for (int ks = 0; ks < 4; ks++) {
            uint32_t kb[4][4];
#pragma unroll
            for (int j = 0; j < 4; j++)
                ldsm_x4(kb[j][0], kb[j][1], kb[j][2], kb[j][3],
                        sb + (uint32_t)(((base + (j * 16 + b_roff) * AST) + ks * 16 + b_coff) * 2));
#pragma unroll
            for (int j = 0; j < 4; j++) {
                mma16816_h(sacc[2 * j],     qf[ks], &kb[j][0]);
                mma16816_h(sacc[2 * j + 1], qf[ks], &kb[j][2]);
            }
        }

        // --- O += P V, rowsum += P ; P = 2^S via packed ex2 on fragments ---
#pragma unroll
        for (int pk = 0; pk < 4; pk++) {
            uint32_t pa[4];
            pa[0] = ex2_f16x2(sacc[2 * pk][0]);
            pa[1] = ex2_f16x2(sacc[2 * pk][1]);
            pa[2] = ex2_f16x2(sacc[2 * pk + 1][0]);
            pa[3] = ex2_f16x2(sacc[2 * pk + 1][1]);
            uint32_t vb[4][4];
#pragma unroll
            for (int dj = 0; dj < 4; dj++)
                ldsm_x4_t(vb[dj][0], vb[dj][1], vb[dj][2], vb[dj][3],
                          sb + (uint32_t)(((base + 64 * AST + (pk * 16 + v_roff) * AST) + dj * 16 + v_coff) * 2));
#pragma unroll
            for (int dj = 0; dj < 4; dj++) {
                mma16816(oacc[2 * dj],     pa, &vb[dj][0]);
                mma16816(oacc[2 * dj + 1], pa, &vb[dj][2]);
            }
            mma16816(oex, pa, vxa);
        }
    }

    // --- rowsum broadcast from quad lane 0 ---
    const float rsum0 = __shfl_sync(0xFFFFFFFFu, oex[0], lid & ~3);
    const float rsum1 = __shfl_sync(0xFFFFFFFFu, oex[2], lid & ~3);
    const float rinv0 = 1.0f / rsum0;
    const float rinv1 = 1.0f / rsum1;

    // --- normalize + write fp16 ---
    const int gr = lid >> 2;
    const int gc = (lid & 3) * 2;
    const size_t row0 = qrow0 + m0 + gr;
#pragma unroll
    for (int nj = 0; nj < 8; nj++) {
        const int col = colb + nj * 8 + gc;
        *(uint32_t*)(og + row0 * 512 + col) =
            pack_f16x2(oacc[nj][0] * rinv0, oacc[nj][1] * rinv0);
        *(uint32_t*)(og + (row0 + 8) * 512 + col) =
            pack_f16x2(oacc[nj][2] * rinv1, oacc[nj][3] * rinv1);
    }
}

// ---------------------------------------------------------------------------
// Launch
// ---------------------------------------------------------------------------
extern "C" void kernel_launch(void* const* d_in, const int* in_sizes, int n_in,
                              void* d_out, int out_size)
{
    (void)in_sizes; (void)n_in; (void)out_size;
    const float* X  = (const float*)d_in[0];
    const float* Wq = (const float*)d_in[2];
    const float* bq = (const float*)d_in[3];
    const float* Wk = (const float*)d_in[4];
    const float* bk = (const float*)d_in[5];
    const float* Wv = (const float*)d_in[6];
    const float* bv = (const float*)d_in[7];
    const float* W1 = (const float*)d_in[8];
    const float* b1 = (const float*)d_in[9];
    const float* W2 = (const float*)d_in[10];
    const float* b2 = (const float*)d_in[11];
    float* out = (float*)d_out;

    __half *x, *q, *k, *v, *ao, *h, *w2;
    cudaGetSymbolAddress((void**)&x,  g_x);
    cudaGetSymbolAddress((void**)&q,  g_q);
    cudaGetSymbolAddress((void**)&k,  g_k);
    cudaGetSymbolAddress((void**)&v,  g_v);
    cudaGetSymbolAddress((void**)&ao, g_ao);
    cudaGetSymbolAddress((void**)&h,  g_h);
    cudaGetSymbolAddress((void**)&w2, g_w2);
    const size_t WSZ = (size_t)GN * GK;

    cudaFuncSetAttribute((const void*)gemm_mma<true, false, 3>,
                         cudaFuncAttributeMaxDynamicSharedMemorySize, GEMM_DSMEM);
    cudaFuncSetAttribute((const void*)gemm_mma<true, false, 1>,
                         cudaFuncAttributeMaxDynamicSharedMemorySize, GEMM_DSMEM);
    cudaFuncSetAttribute((const void*)gemm_mma<false, true, 1>,
                         cudaFuncAttributeMaxDynamicSharedMemorySize, GEMM_DSMEM);
    cudaFuncSetAttribute((const void*)attn_mma,
                         cudaFuncAttributeMaxDynamicSharedMemorySize, ATT_DSMEM);

    const float CEXP = 0.18033688011112042f;   // 0.125 * log2(e)

    dim3 blk128(128);
    dim3 blk256(256);
    dim3 gConv(NXBLK + NWBLK);          // fused X + 5 weights conversion
    dim3 gQKV(3 * GN / BN, GM / BM);    // (12, 384): z fastest for L2 A-reuse
    dim3 gFC(GN / BN, GM / BM);         // (4, 384)
    dim3 gAtt(4, BT * KH);              // (qblock, head): sharers adjacent

    conv_all<<<gConv, blk256>>>(X, x, Wq, Wk, Wv, W1, W2, w2);

    // 1) QKV (fp16 out; q scaled by CEXP)
    gemm_mma<true, false, 3><<<gQKV, blk128, GEMM_DSMEM>>>(x, w2, w2 + WSZ, w2 + 2 * WSZ,
                                                           bq, bk, bv, nullptr, q, k, v, CEXP);
    // 2) attention -> ao (fp16)
    attn_mma<<<gAtt, blk256, ATT_DSMEM>>>(q, k, v, ao);
    // 3) FC1 -> h (fp16, ReLU)
    gemm_mma<true, false, 1><<<gFC, blk128, GEMM_DSMEM>>>(ao, w2 + 3 * WSZ, w2 + 3 * WSZ, w2 + 3 * WSZ,
                                                          b1, b1, b1, nullptr, h, h, h, 1.0f);
    // 4) FC2 -> out (fp32)
    gemm_mma<false, true, 1><<<gFC, blk128, GEMM_DSMEM>>>(h, w2 + 4 * WSZ, w2 + 4 * WSZ, w2 + 4 * WSZ,
                                                          b2, b2, b2, out,
                                                          nullptr, nullptr, nullptr, 1.0f);
}

// round 16
// speedup vs baseline: 1.1117x; 1.0015x over previous
#include <cuda_runtime.h>
#include <cuda_fp16.h>
#include <cstdint>

// ---------------------------------------------------------------------------
// Problem constants
// ---------------------------------------------------------------------------
constexpr int Bc = 8, Tc = 12, Nc = 512;
constexpr int BT = Bc * Tc;                 // 96
constexpr int GM = BT * Nc;                 // 49152 rows
constexpr int GN = 512;
constexpr int GK = 512;
constexpr int KH = 8;

// Scratch (allocation-free rule: __device__ globals)
__device__ __half g_x [(size_t)GM * GK];
__device__ __half g_q [(size_t)GM * GK];
__device__ __half g_k [(size_t)GM * GK];
__device__ __half g_v [(size_t)GM * GK];
__device__ __half g_ao[(size_t)GM * GK];
__device__ __half g_h [(size_t)GM * GK];
__device__ __half g_w2[5 * (size_t)GN * GK];   // fp16 weights, [n][k]

__device__ __forceinline__ uint32_t smem_to_u32(const void* p) {
    uint32_t a;
    asm("{ .reg .u64 t; cvta.to.shared.u64 t, %1; cvt.u32.u64 %0, t; }" : "=r"(a) : "l"(p));
    return a;
}

// ---------------------------------------------------------------------------
// Portable tensor-core primitives (sm_80+ ISA)
// ---------------------------------------------------------------------------
__device__ __forceinline__ void ldsm_x4(uint32_t& r0, uint32_t& r1, uint32_t& r2, uint32_t& r3,
                                        uint32_t addr) {
    asm volatile("ldmatrix.sync.aligned.m8n8.x4.shared.b16 {%0,%1,%2,%3}, [%4];"
                 : "=r"(r0), "=r"(r1), "=r"(r2), "=r"(r3) : "r"(addr));
}
__device__ __forceinline__ void ldsm_x4_t(uint32_t& r0, uint32_t& r1, uint32_t& r2, uint32_t& r3,
                                          uint32_t addr) {
    asm volatile("ldmatrix.sync.aligned.m8n8.x4.trans.shared.b16 {%0,%1,%2,%3}, [%4];"
                 : "=r"(r0), "=r"(r1), "=r"(r2), "=r"(r3) : "r"(addr));
}
__device__ __forceinline__ void mma16816(float* d, const uint32_t* a, const uint32_t* b) {
    asm volatile("mma.sync.aligned.m16n8k16.row.col.f32.f16.f16.f32 "
                 "{%0,%1,%2,%3}, {%4,%5,%6,%7}, {%8,%9}, {%0,%1,%2,%3};"
                 : "+f"(d[0]), "+f"(d[1]), "+f"(d[2]), "+f"(d[3])
                 : "r"(a[0]), "r"(a[1]), "r"(a[2]), "r"(a[3]), "r"(b[0]), "r"(b[1]));
}
// fp16-accumulated variant: D/C are 2 x f16x2 regs; D-fragment layout matches
// the A-fragment layout of a following MMA.
__device__ __forceinline__ void mma16816_h(uint32_t* d, const uint32_t* a, const uint32_t* b) {
    asm volatile("mma.sync.aligned.m16n8k16.row.col.f16.f16.f16.f16 "
                 "{%0,%1}, {%2,%3,%4,%5}, {%6,%7}, {%0,%1};"
                 : "+r"(d[0]), "+r"(d[1])
                 : "r"(a[0]), "r"(a[1]), "r"(a[2]), "r"(a[3]), "r"(b[0]), "r"(b[1]));
}
__device__ __forceinline__ void cp_async16(uint32_t smem_addr, const void* gptr) {
    asm volatile("cp.async.cg.shared.global [%0], [%1], 16;" :: "r"(smem_addr), "l"(gptr));
}
#define CP_COMMIT() asm volatile("cp.async.commit_group;" ::: "memory")
#define CP_WAIT(n)  asm volatile("cp.async.wait_group %0;" :: "n"(n) : "memory")

__device__ __forceinline__ uint32_t pack_f16x2(float lo, float hi) {
    uint32_t r;
    asm("cvt.rn.f16x2.f32 %0, %1, %2;" : "=r"(r) : "f"(hi), "f"(lo));
    return r;
}
__device__ __forceinline__ uint32_t ex2_f16x2(uint32_t x) {
    uint32_t r;
    asm("ex2.approx.f16x2 %0, %1;" : "=r"(r) : "r"(x));
    return r;
}

// ---------------------------------------------------------------------------
// Fused conversion kernel: one launch covers X (fp32->fp16) and all 5 weights
// (fp32 [k][n] -> fp16 [n][k]). Block-range switch.
// ---------------------------------------------------------------------------
constexpr unsigned NXBLK = (unsigned)((size_t)GM * 64 / 256);   // 12288
constexpr unsigned NWBLK = 5 * (512 * 512 / 256);               // 5120

__global__ __launch_bounds__(256)
void conv_all(const float* __restrict__ X, __half* __restrict__ Xh,
              const float* __restrict__ W0, const float* __restrict__ W1,
              const float* __restrict__ W2, const float* __restrict__ W3,
              const float* __restrict__ W4, __half* __restrict__ Wdst)
{
    const unsigned b = blockIdx.x;
    if (b < NXBLK) {
        size_t i = (size_t)b * 256 + threadIdx.x;
        size_t base = i * 8;
        float4 a0 = *(const float4*)(X + base);
        float4 a1 = *(const float4*)(X + base + 4);
        __half h[8];
        h[0] = __float2half_rn(a0.x); h[1] = __float2half_rn(a0.y);
        h[2] = __float2half_rn(a0.z); h[3] = __float2half_rn(a0.w);
        h[4] = __float2half_rn(a1.x); h[5] = __float2half_rn(a1.y);
        h[6] = __float2half_rn(a1.z); h[7] = __float2half_rn(a1.w);
        *(uint4*)(Xh + base) = *(uint4*)h;
    } else {
        const unsigned wb = b - NXBLK;           // 0..5119
        const int z = (int)(wb / 1024);          // weight index
        const float* W = (z == 0) ? W0 : (z == 1) ? W1 : (z == 2) ? W2 : (z == 3) ? W3 : W4;
        __half* d = Wdst + (size_t)z * GN * GK;
        int i = (int)(wb % 1024) * 256 + threadIdx.x;   // 512*512
        int k = i >> 9, n = i & 511;
        d[(size_t)n * GK + k] = __float2half_rn(W[i]);
    }
}

// ---------------------------------------------------------------------------
// HMMA GEMM: CTA 128x128, 128 threads (2x2 warps of 64x64), 2 CTAs/SM,
// 3-stage cp.async, fully-unrolled, and NOW kk-level fragment double
// buffering: next kk's ldsm issued before current kk's MMAs, so exposed
// ldsm latency drops from 4x/it to 1x/it (fix for issue=15.6%, tensor=53%).
// scale0: extra output scale applied when z == 0 (folds exp constant into q).
// ---------------------------------------------------------------------------
constexpr int BM = 128, BN = 128, BK = 64;
constexpr int KST = 72;                       // padded smem stride (fp16 elems)
constexpr int NIT = GK / BK;                  // 8
constexpr int NSTG = 3;
constexpr int STG_ELEMS = (BM + BN) * KST;    // 18432
constexpr int GEMM_DSMEM = NSTG * STG_ELEMS * 2;  // 110592 B (2 CTA = 221 KB)

template <bool RELU, bool F32OUT, int NZ>
__global__ __launch_bounds__(128)
void gemm_mma(const __half* __restrict__ A,
              const __half* __restrict__ B0, const __half* __restrict__ B1,
              const __half* __restrict__ B2,
              const float* __restrict__ bias0, const float* __restrict__ bias1,
              const float* __restrict__ bias2,
              float* __restrict__ F,
              __half* __restrict__ H0, __half* __restrict__ H1, __half* __restrict__ H2,
              float scale0)
{
    const int z  = (NZ == 1) ? 0 : ((int)blockIdx.x % NZ);
    const int nb = (NZ == 1) ? (int)blockIdx.x : ((int)blockIdx.x / NZ);
    const __half* Bw  = (z == 0) ? B0 : (z == 1) ? B1 : B2;
    const float* bias = (z == 0) ? bias0 : (z == 1) ? bias1 : bias2;
    __half* Ho        = (z == 0) ? H0 : (z == 1) ? H1 : H2;
    const float sc    = (z == 0) ? scale0 : 1.0f;

    extern __shared__ __align__(16) __half dynsm[];
    const uint32_t sbase = smem_to_u32(dynsm);

    const int tid = threadIdx.x;
    const int wid = tid >> 5;
    const int lid = tid & 31;
    const int m0 = (wid >> 1) * 64;       // 2 m-warps
    const int n0 = (wid & 1) * 64;        // 2 n-warps

    const size_t mBase = (size_t)blockIdx.y * BM;
    const size_t nBase = (size_t)nb * BN;
    const __half* Ag = A + mBase * GK;
    const __half* Bg = Bw + nBase * GK;

    auto load_stage = [&](int buf, int it) {
        const int k0 = it * BK;
        const uint32_t aOff = sbase + (uint32_t)(buf * STG_ELEMS) * 2;
        const uint32_t bOff = aOff + (uint32_t)(BM * KST) * 2;
#pragma unroll
        for (int p = 0; p < 8; p++) {
            int idx = tid + p * 128;
            int r = idx >> 3, u = (idx & 7) * 8;
            cp_async16(aOff + (uint32_t)((r * KST + u) * 2), Ag + (size_t)r * GK + k0 + u);
        }
#pragma unroll
        for (int p = 0; p < 8; p++) {
            int idx = tid + p * 128;
            int r = idx >> 3, u = (idx & 7) * 8;
            cp_async16(bOff + (uint32_t)((r * KST + u) * 2), Bg + (size_t)r * GK + k0 + u);
        }
        CP_COMMIT();
    };

    float acc[4][8][4];
#pragma unroll
    for (int i = 0; i < 4; i++)
#pragma unroll
        for (int j = 0; j < 8; j++)
#pragma unroll
            for (int c = 0; c < 4; c++) acc[i][j][c] = 0.0f;

    const int seg = lid >> 3, lrow = lid & 7;
    const int a_roff = lrow + ((seg & 1) << 3);
    const int a_coff = (seg >> 1) << 3;
    const int b_roff = lrow + ((seg >> 1) << 3);
    const int b_coff = (seg & 1) << 3;

    // fragment loader (kk-indexed), writes into caller buffers
    auto frag_load = [&](uint32_t (&ra)[4][4], uint32_t (&rb)[4][4],
                         uint32_t aB, uint32_t bB, int kk) {
#pragma unroll
        for (int mi = 0; mi < 4; mi++) {
            uint32_t addr = aB + (uint32_t)(((m0 + mi * 16 + a_roff) * KST + kk * 16 + a_coff) * 2);
            ldsm_x4(ra[mi][0], ra[mi][1], ra[mi][2], ra[mi][3], addr);
        }
#pragma unroll
        for (int g = 0; g < 4; g++) {
            uint32_t addr = bB + (uint32_t)(((n0 + g * 16 + b_roff) * KST + kk * 16 + b_coff) * 2);
            ldsm_x4(rb[g][0], rb[g][1], rb[g][2], rb[g][3], addr);
        }
    };

    load_stage(0, 0);
    load_stage(1, 1);

#pragma unroll
    for (int it = 0; it < NIT; ++it) {
        CP_WAIT(1);
        __syncthreads();
        if (it + 2 < NIT) load_stage((it + 2) % NSTG, it + 2);

        const uint32_t aB = sbase + (uint32_t)((it % NSTG) * STG_ELEMS) * 2;
        const uint32_t bB = aB + (uint32_t)(BM * KST) * 2;

        uint32_t ra[2][4][4], rb[2][4][4];
        frag_load(ra[0], rb[0], aB, bB, 0);

#pragma unroll
        for (int kk = 0; kk < 4; kk++) {
            const int cur = kk & 1;
            const int nxt = cur ^ 1;
            if (kk < 3) frag_load(ra[nxt], rb[nxt], aB, bB, kk + 1);
#pragma unroll
            for (int mi = 0; mi < 4; mi++)
#pragma unroll
                for (int g = 0; g < 4; g++) {
                    mma16816(acc[mi][2 * g],     ra[cur][mi], &rb[cur][g][0]);
                    mma16816(acc[mi][2 * g + 1], ra[cur][mi], &rb[cur][g][2]);
                }
        }
    }

    // epilogue (bias hoisted: columns depend only on nj, not mi)
    const int gr = lid >> 2;
    const int gc = (lid & 3) * 2;
    float bx[8], by[8];
#pragma unroll
    for (int nj = 0; nj < 8; nj++) {
        const int col = (int)nBase + n0 + nj * 8 + gc;
        bx[nj] = __ldg(&bias[col]);
        by[nj] = __ldg(&bias[col + 1]);
    }
#pragma unroll
    for (int mi = 0; mi < 4; mi++) {
        const size_t row0 = mBase + m0 + mi * 16 + gr;
#pragma unroll
        for (int nj = 0; nj < 8; nj++) {
            const int col = (int)nBase + n0 + nj * 8 + gc;
            float v0 = acc[mi][nj][0] + bx[nj];
            float v1 = acc[mi][nj][1] + by[nj];
            float v2 = acc[mi][nj][2] + bx[nj];
            float v3 = acc[mi][nj][3] + by[nj];
            if (RELU) {
                v0 = fmaxf(v0, 0.f); v1 = fmaxf(v1, 0.f);
                v2 = fmaxf(v2, 0.f); v3 = fmaxf(v3, 0.f);
            }
            v0 *= sc; v1 *= sc; v2 *= sc; v3 *= sc;
            if (F32OUT) {
                *(float2*)(F + row0 * GN + col)       = make_float2(v0, v1);
                *(float2*)(F + (row0 + 8) * GN + col) = make_float2(v2, v3);
            } else {
                *(uint32_t*)(Ho + row0 * GN + col)       = pack_f16x2(v0, v1);
                *(uint32_t*)(Ho + (row0 + 8) * GN + col) = pack_f16x2(v2, v3);
            }
        }
    }
}

// ---------------------------------------------------------------------------
// HMMA flash attention (R13 winner, frozen): CTA = 128 queries of one head,
// 256 threads, 8 warps of 16x64, 2 CTA/SM, 4-stage KV pipeline.
// fp16-accumulated S (D-fragment == PV A-fragment), packed ex2 softmax,
// rowsum via constant ones-fragment, q pre-scaled by 0.125*log2(e).
// Grid: x = q-block (4, fast -> KV L2 reuse), y = head (768).
// ---------------------------------------------------------------------------
constexpr int AST = 72;                       // smem row stride (fp16)
constexpr int SQ = 0;
constexpr int SKV0 = 128 * AST;
constexpr int ASTG = 2 * 64 * AST;            // per-stage elems (k, v)
constexpr int ANSTG = 4;
constexpr int ATT_DSMEM = (SKV0 + ANSTG * ASTG) * 2;  // 92160 B (2 CTA = 180 KB)

__global__ __launch_bounds__(256, 2)
void attn_mma(const __half* __restrict__ qg, const __half* __restrict__ kg,
              const __half* __restrict__ vg, __half* __restrict__ og)
{
    extern __shared__ __align__(16) __half smb[];
    const uint32_t sb = smem_to_u32(smb);

    const int tid = threadIdx.x;
    const int wid = tid >> 5;
    const int lid = tid & 31;
    const int m0 = wid * 16;

    const int head = blockIdx.y;
    const int bt = head >> 3;
    const int hk = head & 7;
    const size_t qrow0 = (size_t)bt * 512 + blockIdx.x * 128;
    const size_t krow0 = (size_t)bt * 512;
    const int colb = hk * 64;

    const int seg = lid >> 3, lrow = lid & 7;
    const int a_roff = lrow + ((seg & 1) << 3);
    const int a_coff = (seg >> 1) << 3;
    const int b_roff = lrow + ((seg >> 1) << 3);
    const int b_coff = (seg & 1) << 3;
    const int v_roff = lrow + ((seg & 1) << 3);
    const int v_coff = (seg >> 1) << 3;

    // ---- stage Q (own commit group) ----
    {
#pragma unroll
        for (int t = 0; t < 4; t++) {
            int c = tid + t * 256;              // 1024 chunks
            int r = c >> 3, u = (c & 7) * 8;
            cp_async16(sb + (uint32_t)((SQ + r * AST + u) * 2),
                       qg + (qrow0 + r) * 512 + colb + u);
        }
        CP_COMMIT();
    }
    auto stage_kv = [&](int kt) {
        const size_t kr = krow0 + kt * 64;
        const uint32_t b = SKV0 + (kt % ANSTG) * ASTG;
#pragma unroll
        for (int t = 0; t < 2; t++) {
            int c = tid + t * 256;              // 512 chunks per array
            int r = c >> 3, u = (c & 7) * 8;
            cp_async16(sb + (uint32_t)((b + r * AST + u) * 2),
                       kg + (kr + r) * 512 + colb + u);
            cp_async16(sb + (uint32_t)((b + 64 * AST + r * AST + u) * 2),
                       vg + (kr + r) * 512 + colb + u);
        }
        CP_COMMIT();
    };

    stage_kv(0);
    stage_kv(1);
    stage_kv(2);
    CP_WAIT(3);          // Q complete (oldest of 4 groups)
    __syncthreads();

    // ---- Q fragments ----
    uint32_t qf[4][4];
#pragma unroll
    for (int ks = 0; ks < 4; ks++)
        ldsm_x4(qf[ks][0], qf[ks][1], qf[ks][2], qf[ks][3],
                sb + (uint32_t)(((SQ + (m0 + a_roff) * AST) + ks * 16 + a_coff) * 2));

    float oacc[8][4];
#pragma unroll
    for (int j = 0; j < 8; j++)
#pragma unroll
        for (int c = 0; c < 4; c++) oacc[j][c] = 0.0f;
    float oex[4] = {0.f, 0.f, 0.f, 0.f};       // rowsum via ones-fragment

    // ones B-fragment: local col 0 = 1.0 for all k -> lanes 0-3 hold 1.0h pairs
    const uint32_t vxc = (lid < 4) ? 0x3C003C00u : 0u;
    uint32_t vxa[2] = {vxc, vxc};

#pragma unroll
    for (int kt = 0; kt < 8; kt++) {
        CP_WAIT(2);                 // stage kt ready
        __syncthreads();
        if (kt + 3 < 8) stage_kv(kt + 3);

        const uint32_t base = SKV0 + (kt % ANSTG) * ASTG;

        // --- S = Q K^T in fp16 accumulation (q carries 0.125*log2e) ---
        uint32_t sacc[8][2];
#pragma unroll
        for (int j = 0; j < 8; j++) { sacc[j][0] = 0u; sacc[j][1] = 0u; }

#pragma unroll
        for (int ks = 0; ks < 4; ks++) {
            uint32_t kb[4][4];
#pragma unroll
            for (int j = 0; j < 4; j++)
                ldsm_x4(kb[j][0], kb[j][1], kb[j][2], kb[j][3],
                        sb + (uint32_t)(((base + (j * 16 + b_roff) * AST) + ks * 16 + b_coff) * 2));
#pragma unroll
            for (int j = 0; j < 4; j++) {
                mma16816_h(sacc[2 * j],     qf[ks], &kb[j][0]);
                mma16816_h(sacc[2 * j + 1], qf[ks], &kb[j][2]);
            }
        }

        // --- O += P V, rowsum += P ; P = 2^S via packed ex2 on fragments ---
#pragma unroll
        for (int pk = 0; pk < 4; pk++) {
            uint32_t pa[4];
            pa[0] = ex2_f16x2(sacc[2 * pk][0]);
            pa[1] = ex2_f16x2(sacc[2 * pk][1]);
            pa[2] = ex2_f16x2(sacc[2 * pk + 1][0]);
            pa[3] = ex2_f16x2(sacc[2 * pk + 1][1]);
            uint32_t vb[4][4];
#pragma unroll
            for (int dj = 0; dj < 4; dj++)
                ldsm_x4_t(vb[dj][0], vb[dj][1], vb[dj][2], vb[dj][3],
                          sb + (uint32_t)(((base + 64 * AST + (pk * 16 + v_roff) * AST) + dj * 16 + v_coff) * 2));
#pragma unroll
            for (int dj = 0; dj < 4; dj++) {
                mma16816(oacc[2 * dj],     pa, &vb[dj][0]);
                mma16816(oacc[2 * dj + 1], pa, &vb[dj][2]);
            }
            mma16816(oex, pa, vxa);
        }
    }

    // --- rowsum broadcast from quad lane 0 ---
    const float rsum0 = __shfl_sync(0xFFFFFFFFu, oex[0], lid & ~3);
    const float rsum1 = __shfl_sync(0xFFFFFFFFu, oex[2], lid & ~3);
    const float rinv0 = 1.0f / rsum0;
    const float rinv1 = 1.0f / rsum1;

    // --- normalize + write fp16 ---
    const int gr = lid >> 2;
    const int gc = (lid & 3) * 2;
    const size_t row0 = qrow0 + m0 + gr;
#pragma unroll
    for (int nj = 0; nj < 8; nj++) {
        const int col = colb + nj * 8 + gc;
        *(uint32_t*)(og + row0 * 512 + col) =
            pack_f16x2(oacc[nj][0] * rinv0, oacc[nj][1] * rinv0);
        *(uint32_t*)(og + (row0 + 8) * 512 + col) =
            pack_f16x2(oacc[nj][2] * rinv1, oacc[nj][3] * rinv1);
    }
}

// ---------------------------------------------------------------------------
// Launch
// ---------------------------------------------------------------------------
extern "C" void kernel_launch(void* const* d_in, const int* in_sizes, int n_in,
                              void* d_out, int out_size)
{
    (void)in_sizes; (void)n_in; (void)out_size;
    const float* X  = (const float*)d_in[0];
    const float* Wq = (const float*)d_in[2];
    const float* bq = (const float*)d_in[3];
    const float* Wk = (const float*)d_in[4];
    const float* bk = (const float*)d_in[5];
    const float* Wv = (const float*)d_in[6];
    const float* bv = (const float*)d_in[7];
    const float* W1 = (const float*)d_in[8];
    const float* b1 = (const float*)d_in[9];
    const float* W2 = (const float*)d_in[10];
    const float* b2 = (const float*)d_in[11];
    float* out = (float*)d_out;

    __half *x, *q, *k, *v, *ao, *h, *w2;
    cudaGetSymbolAddress((void**)&x,  g_x);
    cudaGetSymbolAddress((void**)&q,  g_q);
    cudaGetSymbolAddress((void**)&k,  g_k);
    cudaGetSymbolAddress((void**)&v,  g_v);
    cudaGetSymbolAddress((void**)&ao, g_ao);
    cudaGetSymbolAddress((void**)&h,  g_h);
    cudaGetSymbolAddress((void**)&w2, g_w2);
    const size_t WSZ = (size_t)GN * GK;

    cudaFuncSetAttribute((const void*)gemm_mma<true, false, 3>,
                         cudaFuncAttributeMaxDynamicSharedMemorySize, GEMM_DSMEM);
    cudaFuncSetAttribute((const void*)gemm_mma<true, false, 1>,
                         cudaFuncAttributeMaxDynamicSharedMemorySize, GEMM_DSMEM);
    cudaFuncSetAttribute((const void*)gemm_mma<false, true, 1>,
                         cudaFuncAttributeMaxDynamicSharedMemorySize, GEMM_DSMEM);
    cudaFuncSetAttribute((const void*)attn_mma,
                         cudaFuncAttributeMaxDynamicSharedMemorySize, ATT_DSMEM);

    const float CEXP = 0.18033688011112042f;   // 0.125 * log2(e)

    dim3 blk128(128);
    dim3 blk256(256);
    dim3 gConv(NXBLK + NWBLK);          // fused X + 5 weights conversion
    dim3 gQKV(3 * GN / BN, GM / BM);    // (12, 384): z fastest for L2 A-reuse
    dim3 gFC(GN / BN, GM / BM);         // (4, 384)
    dim3 gAtt(4, BT * KH);              // (qblock, head): sharers adjacent

    conv_all<<<gConv, blk256>>>(X, x, Wq, Wk, Wv, W1, W2, w2);

    // 1) QKV (fp16 out; q scaled by CEXP)
    gemm_mma<true, false, 3><<<gQKV, blk128, GEMM_DSMEM>>>(x, w2, w2 + WSZ, w2 + 2 * WSZ,
                                                           bq, bk, bv, nullptr, q, k, v, CEXP);
    // 2) attention -> ao (fp16)
    attn_mma<<<gAtt, blk256, ATT_DSMEM>>>(q, k, v, ao);
    // 3) FC1 -> h (fp16, ReLU)
    gemm_mma<true, false, 1><<<gFC, blk128, GEMM_DSMEM>>>(ao, w2 + 3 * WSZ, w2 + 3 * WSZ, w2 + 3 * WSZ,
                                                          b1, b1, b1, nullptr, h, h, h, 1.0f);
    // 4) FC2 -> out (fp32)
    gemm_mma<false, true, 1><<<gFC, blk128, GEMM_DSMEM>>>(h, w2 + 4 * WSZ, w2 + 4 * WSZ, w2 + 4 * WSZ,
                                                          b2, b2, b2, out,
                                                          nullptr, nullptr, nullptr, 1.0f);
}